// round 1
// baseline (speedup 1.0000x reference)
#include <cuda_runtime.h>
#include <math.h>

// Problem shape (fixed by reference): z (16,768,64,64), memory (1024,768)
#define B_  16
#define C_  768
#define N_  4096      // H*W
#define BN_ 65536     // B*N
#define M_  1024

#define TM 128
#define TN 128
#define TK 16

// scratch: reciprocal row norms (allocation-free per harness rules)
__device__ float g_rz[BN_];
__device__ float g_rm[M_];

// ---------------------------------------------------------------------------
// Kernel 1: 1/||z_row|| for each (b, n). z layout (B, C, N): stride N per c,
// consecutive threads take consecutive n -> fully coalesced.
// ---------------------------------------------------------------------------
__global__ void k_rnorm_z(const float* __restrict__ z) {
    int row = blockIdx.x * blockDim.x + threadIdx.x;  // 0..BN_-1
    int b = row >> 12;
    int n = row & (N_ - 1);
    const float* p = z + (size_t)b * (C_ * N_) + n;
    float acc = 0.f;
#pragma unroll 16
    for (int c = 0; c < C_; ++c) {
        float v = __ldg(p + (size_t)c * N_);
        acc = fmaf(v, v, acc);
    }
    g_rz[row] = 1.0f / fmaxf(sqrtf(acc), 1e-12f);
}

// ---------------------------------------------------------------------------
// Kernel 2: 1/||memory_row|| (one block per row, contiguous reads)
// ---------------------------------------------------------------------------
__global__ void k_rnorm_m(const float* __restrict__ mem) {
    int m = blockIdx.x;
    const float* p = mem + m * C_;
    float acc = 0.f;
    for (int c = threadIdx.x; c < C_; c += 128) {
        float v = p[c];
        acc = fmaf(v, v, acc);
    }
#pragma unroll
    for (int o = 16; o; o >>= 1) acc += __shfl_xor_sync(0xffffffffu, acc, o);
    __shared__ float s[4];
    if ((threadIdx.x & 31) == 0) s[threadIdx.x >> 5] = acc;
    __syncthreads();
    if (threadIdx.x == 0) {
        float t = s[0] + s[1] + s[2] + s[3];
        g_rm[m] = 1.0f / fmaxf(sqrtf(t), 1e-12f);
    }
}

// ---------------------------------------------------------------------------
// Kernel 3: scores[bn, m] = rz[bn]*rm[m]*sum_c z[b,c,n]*mem[m,c]
// z is naturally K-major (c-strided) for the A tile; mem is row-major [M][C]
// so the B tile is transposed into smem on load.
// 128x128x16 tile, 256 threads, 8x8 per thread.
// ---------------------------------------------------------------------------
__global__ void __launch_bounds__(256) k_gemm1(const float* __restrict__ z,
                                               const float* __restrict__ mem,
                                               float* __restrict__ scores) {
    __shared__ float As[TK][TM];       // [k][n]
    __shared__ float Bs[TK][TN + 4];   // [k][m], pad keeps 16B alignment, kills conflicts
    const int tid = threadIdx.x;
    const int tx = tid & 15;
    const int ty = tid >> 4;
    const int m0 = blockIdx.x * TN;
    const int row0 = blockIdx.y * TM;       // bn-row (never crosses batch: 4096%128==0)
    const int b = row0 >> 12;
    const int n0 = row0 & (N_ - 1);
    const float* zb = z + (size_t)b * (C_ * N_) + n0;

    float acc[8][8];
#pragma unroll
    for (int i = 0; i < 8; ++i)
#pragma unroll
        for (int j = 0; j < 8; ++j) acc[i][j] = 0.f;

    for (int k0 = 0; k0 < C_; k0 += TK) {
        // A: 16x128 floats, float4, coalesced per k-row
#pragma unroll
        for (int p = 0; p < 2; ++p) {
            int f = tid + p * 256;
            int kk = f >> 5, n4 = (f & 31) << 2;
            float4 v = *(const float4*)(zb + (size_t)(k0 + kk) * N_ + n4);
            *(float4*)&As[kk][n4] = v;
        }
        // B: 128 rows x 16 k, float4 along k, transposed store
#pragma unroll
        for (int p = 0; p < 2; ++p) {
            int f = tid + p * 256;
            int j = f >> 2, kc = (f & 3) << 2;
            float4 v = *(const float4*)(mem + (size_t)(m0 + j) * C_ + k0 + kc);
            Bs[kc + 0][j] = v.x;
            Bs[kc + 1][j] = v.y;
            Bs[kc + 2][j] = v.z;
            Bs[kc + 3][j] = v.w;
        }
        __syncthreads();
#pragma unroll
        for (int k = 0; k < TK; ++k) {
            float a[8], bb[8];
            *(float4*)(a)      = *(const float4*)&As[k][ty * 8];
            *(float4*)(a + 4)  = *(const float4*)&As[k][ty * 8 + 4];
            *(float4*)(bb)     = *(const float4*)&Bs[k][tx * 8];
            *(float4*)(bb + 4) = *(const float4*)&Bs[k][tx * 8 + 4];
#pragma unroll
            for (int i = 0; i < 8; ++i)
#pragma unroll
                for (int j = 0; j < 8; ++j)
                    acc[i][j] = fmaf(a[i], bb[j], acc[i][j]);
        }
        __syncthreads();
    }

    float rmv[8];
#pragma unroll
    for (int j = 0; j < 8; ++j) rmv[j] = g_rm[m0 + tx * 8 + j];
#pragma unroll
    for (int i = 0; i < 8; ++i) {
        float rz = g_rz[row0 + ty * 8 + i];
        float* out = scores + (size_t)(row0 + ty * 8 + i) * M_ + m0 + tx * 8;
        float4 o0, o1;
        o0.x = acc[i][0] * rz * rmv[0];
        o0.y = acc[i][1] * rz * rmv[1];
        o0.z = acc[i][2] * rz * rmv[2];
        o0.w = acc[i][3] * rz * rmv[3];
        o1.x = acc[i][4] * rz * rmv[4];
        o1.y = acc[i][5] * rz * rmv[5];
        o1.z = acc[i][6] * rz * rmv[6];
        o1.w = acc[i][7] * rz * rmv[7];
        *(float4*)(out)     = o0;
        *(float4*)(out + 4) = o1;
    }
}

// ---------------------------------------------------------------------------
// Kernel 4: row softmax over M=1024, in place. One block (128 thr) per row,
// 8 values/thread held in registers, two block reductions (max, sum).
// ---------------------------------------------------------------------------
__global__ void k_softmax(float* __restrict__ attn) {
    const size_t row = blockIdx.x;
    float* p = attn + row * M_;
    const int t = threadIdx.x;
    float v[8];
    *(float4*)(v)     = *(const float4*)(p + t * 8);
    *(float4*)(v + 4) = *(const float4*)(p + t * 8 + 4);

    float mx = v[0];
#pragma unroll
    for (int i = 1; i < 8; ++i) mx = fmaxf(mx, v[i]);
#pragma unroll
    for (int o = 16; o; o >>= 1) mx = fmaxf(mx, __shfl_xor_sync(0xffffffffu, mx, o));
    __shared__ float red[4];
    if ((t & 31) == 0) red[t >> 5] = mx;
    __syncthreads();
    mx = fmaxf(fmaxf(red[0], red[1]), fmaxf(red[2], red[3]));
    __syncthreads();

    float sum = 0.f;
#pragma unroll
    for (int i = 0; i < 8; ++i) {
        v[i] = expf(v[i] - mx);
        sum += v[i];
    }
#pragma unroll
    for (int o = 16; o; o >>= 1) sum += __shfl_xor_sync(0xffffffffu, sum, o);
    if ((t & 31) == 0) red[t >> 5] = sum;
    __syncthreads();
    sum = red[0] + red[1] + red[2] + red[3];
    float r = 1.0f / sum;
#pragma unroll
    for (int i = 0; i < 8; ++i) v[i] *= r;
    *(float4*)(p + t * 8)     = *(const float4*)(v);
    *(float4*)(p + t * 8 + 4) = *(const float4*)(v + 4);
}

// ---------------------------------------------------------------------------
// Kernel 5: z_hat[b,c,n] = sum_m attn[bn,m]*mem[m,c]
// attn tile transposed into smem; mem is already K-major ([m][c]).
// Epilogue transposes through smem so the (c-strided) output writes stay
// coalesced along n.
// ---------------------------------------------------------------------------
__global__ void __launch_bounds__(256) k_gemm2(const float* __restrict__ attn,
                                               const float* __restrict__ mem,
                                               float* __restrict__ zhat) {
    __shared__ float As[TK][TM + 4];     // [k=m][row]
    __shared__ float Bs[TK][TN];         // [k][c]
    __shared__ float stg[32][TM + 1];    // epilogue transpose staging
    const int tid = threadIdx.x;
    const int tx = tid & 15;
    const int ty = tid >> 4;
    const int c0 = blockIdx.x * TN;      // 0..5 * 128
    const int row0 = blockIdx.y * TM;
    const int b = row0 >> 12;
    const int n0 = row0 & (N_ - 1);

    float acc[8][8];
#pragma unroll
    for (int i = 0; i < 8; ++i)
#pragma unroll
        for (int j = 0; j < 8; ++j) acc[i][j] = 0.f;

    for (int k0 = 0; k0 < M_; k0 += TK) {
        // A: attn rows, float4 along m, transposed store
#pragma unroll
        for (int p = 0; p < 2; ++p) {
            int f = tid + p * 256;
            int r = f >> 2, kc = (f & 3) << 2;
            float4 v = *(const float4*)(attn + (size_t)(row0 + r) * M_ + k0 + kc);
            As[kc + 0][r] = v.x;
            As[kc + 1][r] = v.y;
            As[kc + 2][r] = v.z;
            As[kc + 3][r] = v.w;
        }
        // B: mem[k][c], already K-major, direct float4
#pragma unroll
        for (int p = 0; p < 2; ++p) {
            int f = tid + p * 256;
            int kk = f >> 5, j4 = (f & 31) << 2;
            float4 v = *(const float4*)(mem + (size_t)(k0 + kk) * C_ + c0 + j4);
            *(float4*)&Bs[kk][j4] = v;
        }
        __syncthreads();
#pragma unroll
        for (int k = 0; k < TK; ++k) {
            float a[8], bb[8];
            *(float4*)(a)      = *(const float4*)&As[k][ty * 8];
            *(float4*)(a + 4)  = *(const float4*)&As[k][ty * 8 + 4];
            *(float4*)(bb)     = *(const float4*)&Bs[k][tx * 8];
            *(float4*)(bb + 4) = *(const float4*)&Bs[k][tx * 8 + 4];
#pragma unroll
            for (int i = 0; i < 8; ++i)
#pragma unroll
                for (int j = 0; j < 8; ++j)
                    acc[i][j] = fmaf(a[i], bb[j], acc[i][j]);
        }
        __syncthreads();
    }

    // Epilogue: stage 32 c-columns at a time, write coalesced along n.
#pragma unroll
    for (int s = 0; s < 4; ++s) {
        __syncthreads();
        if ((tx >> 2) == s) {
            int cb = (tx & 3) * 8;
#pragma unroll
            for (int j = 0; j < 8; ++j)
#pragma unroll
                for (int i = 0; i < 8; ++i)
                    stg[cb + j][ty * 8 + i] = acc[i][j];
        }
        __syncthreads();
        float* outb = zhat + (size_t)b * (C_ * N_) + (size_t)(c0 + s * 32) * N_ + n0;
#pragma unroll
        for (int e = tid; e < 32 * 128; e += 256) {
            int cl = e >> 7, nl = e & 127;
            outb[(size_t)cl * N_ + nl] = stg[cl][nl];
        }
    }
}

// ---------------------------------------------------------------------------
extern "C" void kernel_launch(void* const* d_in, const int* in_sizes, int n_in,
                              void* d_out, int out_size) {
    const float* z   = (const float*)d_in[0];   // (16,768,64,64)
    const float* mem = (const float*)d_in[1];   // (1024,768)
    float* zhat = (float*)d_out;                          // first output
    float* attn = zhat + (size_t)B_ * C_ * N_;            // second output

    k_rnorm_z<<<BN_ / 256, 256>>>(z);
    k_rnorm_m<<<M_, 128>>>(mem);
    k_gemm1<<<dim3(M_ / TN, BN_ / TM), 256>>>(z, mem, attn);
    k_softmax<<<BN_, 128>>>(attn);
    k_gemm2<<<dim3(C_ / TN, BN_ / TM), 256>>>(attn, mem, zhat);
}

// round 2
// speedup vs baseline: 3.2689x; 3.2689x over previous
#include <cuda_runtime.h>
#include <math.h>
#include <stdint.h>

// shapes fixed by reference
#define B_  16
#define C_  768
#define N_  4096
#define BN_ 65536
#define M_  1024

#define KC  32                 // K chunk per mainloop iter
#define PAD_KM 136             // rows of 128 padded +8 (k-major tiles)
#define PAD_NK 36              // rows of 32  padded +4 (n/row-major tiles)
#define SMEM_BYTES ((2*32*PAD_KM + 2*128*PAD_NK) * 4)   // 71680

// scratch (allocation-free)
__device__ float g_rz[BN_];
__device__ float g_rm[M_];
__device__ float g_memr[M_ * C_];   // memory rounded to tf32 (RN)

// ---------------------------------------------------------------------------
__device__ __forceinline__ void cp16(void* s, const void* g) {
    uint32_t sa = (uint32_t)__cvta_generic_to_shared(s);
    asm volatile("cp.async.cg.shared.global [%0], [%1], 16;\n" :: "r"(sa), "l"(g));
}
__device__ __forceinline__ void cp_commit() {
    asm volatile("cp.async.commit_group;\n" ::: "memory");
}
__device__ __forceinline__ void cp_wait_all() {
    asm volatile("cp.async.wait_group 0;\n" ::: "memory");
}
__device__ __forceinline__ float tf32_rn(float x) {
    uint32_t u;
    asm("cvt.rna.tf32.f32 %0, %1;\n" : "=r"(u) : "f"(x));
    return __uint_as_float(u);
}
__device__ __forceinline__ void mma8(float* d, const uint32_t* a, const uint32_t* b) {
    asm volatile(
        "mma.sync.aligned.m16n8k8.row.col.f32.tf32.tf32.f32 "
        "{%0,%1,%2,%3}, {%4,%5,%6,%7}, {%8,%9}, {%0,%1,%2,%3};\n"
        : "+f"(d[0]), "+f"(d[1]), "+f"(d[2]), "+f"(d[3])
        : "r"(a[0]), "r"(a[1]), "r"(a[2]), "r"(a[3]), "r"(b[0]), "r"(b[1]));
}

// ---------------------------------------------------------------------------
// 1/||z_row||  (z layout (B,C,N): coalesced along n)
__global__ void k_rnorm_z(const float* __restrict__ z) {
    int row = blockIdx.x * blockDim.x + threadIdx.x;
    int b = row >> 12, n = row & (N_ - 1);
    const float* p = z + (size_t)b * (C_ * N_) + n;
    float acc = 0.f;
#pragma unroll 16
    for (int c = 0; c < C_; ++c) {
        float v = __ldg(p + (size_t)c * N_);
        acc = fmaf(v, v, acc);
    }
    g_rz[row] = 1.0f / fmaxf(sqrtf(acc), 1e-12f);
}

// 1/||memory_row||
__global__ void k_rnorm_m(const float* __restrict__ mem) {
    int m = blockIdx.x;
    const float* p = mem + m * C_;
    float acc = 0.f;
    for (int c = threadIdx.x; c < C_; c += 128) {
        float v = p[c];
        acc = fmaf(v, v, acc);
    }
#pragma unroll
    for (int o = 16; o; o >>= 1) acc += __shfl_xor_sync(0xffffffffu, acc, o);
    __shared__ float s[4];
    if ((threadIdx.x & 31) == 0) s[threadIdx.x >> 5] = acc;
    __syncthreads();
    if (threadIdx.x == 0)
        g_rm[m] = 1.0f / fmaxf(sqrtf(s[0] + s[1] + s[2] + s[3]), 1e-12f);
}

// memory rounded to tf32-RN (so HMMA truncation is exact)
__global__ void k_round_mem(const float* __restrict__ mem) {
    int i = blockIdx.x * blockDim.x + threadIdx.x;
    if (i < M_ * C_) g_memr[i] = tf32_rn(mem[i]);
}

// ---------------------------------------------------------------------------
// GEMM1: scores[bn, m] = rz[bn]*rm[m] * sum_c z[b,c,n] * memr[m,c]
// A (z) staged k-major As[k][m]; B (memr) staged Bs[n][k].
// ---------------------------------------------------------------------------
__global__ void __launch_bounds__(256) k_gemm1_t(const float* __restrict__ z,
                                                 float* __restrict__ scores) {
    extern __shared__ float sm[];
    float* As = sm;                    // 2 buffers of [32][PAD_KM]
    float* Bs = sm + 2 * 32 * PAD_KM;  // 2 buffers of [128][PAD_NK]

    const int tid = threadIdx.x;
    const int lane = tid & 31, warp = tid >> 5;
    const int g = lane >> 2, tg = lane & 3;
    const int wm = warp >> 2, wn = warp & 3;
    const int m0 = blockIdx.x * 128;
    const int row0 = blockIdx.y * 128;
    const int b = row0 >> 12, n0 = row0 & (N_ - 1);
    const float* zb = z + (size_t)b * (C_ * N_) + n0;

    float acc[4][4][4];
#pragma unroll
    for (int i = 0; i < 4; ++i)
#pragma unroll
        for (int j = 0; j < 4; ++j)
#pragma unroll
            for (int c = 0; c < 4; ++c) acc[i][j][c] = 0.f;

    const int T = C_ / KC;  // 24
    // ---- preload tile 0
    {
        float* A = As; float* Bq = Bs;
#pragma unroll
        for (int p = 0; p < 4; ++p) {
            int q = tid + p * 256;
            int kk = q >> 5, mc = (q & 31) << 2;
            cp16(A + kk * PAD_KM + mc, zb + (size_t)kk * N_ + mc);
        }
#pragma unroll
        for (int p = 0; p < 4; ++p) {
            int q = tid + p * 256;
            int nn = q >> 3, kc = (q & 7) << 2;
            cp16(Bq + nn * PAD_NK + kc, g_memr + (size_t)(m0 + nn) * C_ + kc);
        }
        cp_commit();
    }

    for (int it = 0; it < T; ++it) {
        cp_wait_all();
        __syncthreads();
        if (it + 1 < T) {
            int k0 = (it + 1) * KC;
            float* A = As + ((it + 1) & 1) * (32 * PAD_KM);
            float* Bq = Bs + ((it + 1) & 1) * (128 * PAD_NK);
#pragma unroll
            for (int p = 0; p < 4; ++p) {
                int q = tid + p * 256;
                int kk = q >> 5, mc = (q & 31) << 2;
                cp16(A + kk * PAD_KM + mc, zb + (size_t)(k0 + kk) * N_ + mc);
            }
#pragma unroll
            for (int p = 0; p < 4; ++p) {
                int q = tid + p * 256;
                int nn = q >> 3, kc = (q & 7) << 2;
                cp16(Bq + nn * PAD_NK + kc, g_memr + (size_t)(m0 + nn) * C_ + k0 + kc);
            }
            cp_commit();
        }
        const float* A = As + (it & 1) * (32 * PAD_KM);
        const float* Bq = Bs + (it & 1) * (128 * PAD_NK);
#pragma unroll
        for (int kk = 0; kk < KC; kk += 8) {
            uint32_t af[4][4], bf[4][2];
#pragma unroll
            for (int mt = 0; mt < 4; ++mt) {
                const float* pa = A + (kk + tg) * PAD_KM + wm * 64 + mt * 16 + g;
                af[mt][0] = __float_as_uint(pa[0]);
                af[mt][1] = __float_as_uint(pa[8]);
                af[mt][2] = __float_as_uint(pa[4 * PAD_KM]);
                af[mt][3] = __float_as_uint(pa[4 * PAD_KM + 8]);
            }
#pragma unroll
            for (int nt = 0; nt < 4; ++nt) {
                const float* pb = Bq + (wn * 32 + nt * 8 + g) * PAD_NK + kk + tg;
                bf[nt][0] = __float_as_uint(pb[0]);
                bf[nt][1] = __float_as_uint(pb[4]);
            }
#pragma unroll
            for (int mt = 0; mt < 4; ++mt)
#pragma unroll
                for (int nt = 0; nt < 4; ++nt) mma8(acc[mt][nt], af[mt], bf[nt]);
        }
        __syncthreads();
    }

    // epilogue: scale by rz*rm, float2 stores (32B sectors per 4-lane group)
#pragma unroll
    for (int mt = 0; mt < 4; ++mt) {
        int r = row0 + wm * 64 + mt * 16 + g;
        float rz0 = g_rz[r], rz1 = g_rz[r + 8];
#pragma unroll
        for (int nt = 0; nt < 4; ++nt) {
            int col = m0 + wn * 32 + nt * 8 + 2 * tg;
            float rm0 = g_rm[col], rm1 = g_rm[col + 1];
            float2 o;
            o.x = acc[mt][nt][0] * rz0 * rm0;
            o.y = acc[mt][nt][1] * rz0 * rm1;
            *(float2*)(scores + (size_t)r * M_ + col) = o;
            o.x = acc[mt][nt][2] * rz1 * rm0;
            o.y = acc[mt][nt][3] * rz1 * rm1;
            *(float2*)(scores + (size_t)(r + 8) * M_ + col) = o;
        }
    }
}

// ---------------------------------------------------------------------------
// softmax over M=1024 per row, in place; emits tf32-RN-rounded weights so
// GEMM2's HMMA truncation is exact.
// ---------------------------------------------------------------------------
__global__ void k_softmax(float* __restrict__ attn) {
    const size_t row = blockIdx.x;
    float* p = attn + row * M_;
    const int t = threadIdx.x;
    float v[8];
    *(float4*)(v)     = *(const float4*)(p + t * 8);
    *(float4*)(v + 4) = *(const float4*)(p + t * 8 + 4);

    float mx = v[0];
#pragma unroll
    for (int i = 1; i < 8; ++i) mx = fmaxf(mx, v[i]);
#pragma unroll
    for (int o = 16; o; o >>= 1) mx = fmaxf(mx, __shfl_xor_sync(0xffffffffu, mx, o));
    __shared__ float red[4];
    if ((t & 31) == 0) red[t >> 5] = mx;
    __syncthreads();
    mx = fmaxf(fmaxf(red[0], red[1]), fmaxf(red[2], red[3]));
    __syncthreads();

    float sum = 0.f;
#pragma unroll
    for (int i = 0; i < 8; ++i) {
        v[i] = expf(v[i] - mx);
        sum += v[i];
    }
#pragma unroll
    for (int o = 16; o; o >>= 1) sum += __shfl_xor_sync(0xffffffffu, sum, o);
    if ((t & 31) == 0) red[t >> 5] = sum;
    __syncthreads();
    sum = red[0] + red[1] + red[2] + red[3];
    float r = 1.0f / sum;
#pragma unroll
    for (int i = 0; i < 8; ++i) v[i] = tf32_rn(v[i] * r);
    *(float4*)(p + t * 8)     = *(const float4*)(v);
    *(float4*)(p + t * 8 + 4) = *(const float4*)(v + 4);
}

// ---------------------------------------------------------------------------
// GEMM2: zhat[b,c,n] = sum_m attn[bn,m] * memr[m,c]
// A (attn) staged As[row][k]; B (memr) staged k-major Bs[k][c].
// ---------------------------------------------------------------------------
__global__ void __launch_bounds__(256) k_gemm2_t(const float* __restrict__ attn,
                                                 float* __restrict__ zhat) {
    extern __shared__ float sm[];
    float* As = sm;                     // 2 buffers of [128][PAD_NK]
    float* Bs = sm + 2 * 128 * PAD_NK;  // 2 buffers of [32][PAD_KM]

    const int tid = threadIdx.x;
    const int lane = tid & 31, warp = tid >> 5;
    const int g = lane >> 2, tg = lane & 3;
    const int wm = warp >> 2, wn = warp & 3;
    const int c0 = blockIdx.x * 128;
    const int row0 = blockIdx.y * 128;
    const int b = row0 >> 12, n0 = row0 & (N_ - 1);

    float acc[4][4][4];
#pragma unroll
    for (int i = 0; i < 4; ++i)
#pragma unroll
        for (int j = 0; j < 4; ++j)
#pragma unroll
            for (int c = 0; c < 4; ++c) acc[i][j][c] = 0.f;

    const int T = M_ / KC;  // 32
    {
        float* A = As; float* Bq = Bs;
#pragma unroll
        for (int p = 0; p < 4; ++p) {
            int q = tid + p * 256;
            int rr = q >> 3, kc = (q & 7) << 2;
            cp16(A + rr * PAD_NK + kc, attn + (size_t)(row0 + rr) * M_ + kc);
        }
#pragma unroll
        for (int p = 0; p < 4; ++p) {
            int q = tid + p * 256;
            int kk = q >> 5, nc = (q & 31) << 2;
            cp16(Bq + kk * PAD_KM + nc, g_memr + (size_t)kk * C_ + c0 + nc);
        }
        cp_commit();
    }

    for (int it = 0; it < T; ++it) {
        cp_wait_all();
        __syncthreads();
        if (it + 1 < T) {
            int k0 = (it + 1) * KC;
            float* A = As + ((it + 1) & 1) * (128 * PAD_NK);
            float* Bq = Bs + ((it + 1) & 1) * (32 * PAD_KM);
#pragma unroll
            for (int p = 0; p < 4; ++p) {
                int q = tid + p * 256;
                int rr = q >> 3, kc = (q & 7) << 2;
                cp16(A + rr * PAD_NK + kc, attn + (size_t)(row0 + rr) * M_ + k0 + kc);
            }
#pragma unroll
            for (int p = 0; p < 4; ++p) {
                int q = tid + p * 256;
                int kk = q >> 5, nc = (q & 31) << 2;
                cp16(Bq + kk * PAD_KM + nc, g_memr + (size_t)(k0 + kk) * C_ + c0 + nc);
            }
            cp_commit();
        }
        const float* A = As + (it & 1) * (128 * PAD_NK);
        const float* Bq = Bs + (it & 1) * (32 * PAD_KM);
#pragma unroll
        for (int kk = 0; kk < KC; kk += 8) {
            uint32_t af[4][4], bf[4][2];
#pragma unroll
            for (int mt = 0; mt < 4; ++mt) {
                const float* pa = A + (wm * 64 + mt * 16 + g) * PAD_NK + kk + tg;
                af[mt][0] = __float_as_uint(pa[0]);
                af[mt][1] = __float_as_uint(pa[8 * PAD_NK]);
                af[mt][2] = __float_as_uint(pa[4]);
                af[mt][3] = __float_as_uint(pa[8 * PAD_NK + 4]);
            }
#pragma unroll
            for (int nt = 0; nt < 4; ++nt) {
                const float* pb = Bq + (kk + tg) * PAD_KM + wn * 32 + nt * 8 + g;
                bf[nt][0] = __float_as_uint(pb[0]);
                bf[nt][1] = __float_as_uint(pb[4 * PAD_KM]);
            }
#pragma unroll
            for (int mt = 0; mt < 4; ++mt)
#pragma unroll
                for (int nt = 0; nt < 4; ++nt) mma8(acc[mt][nt], af[mt], bf[nt]);
        }
        __syncthreads();
    }

    // epilogue: output (b, c, n); 8 consecutive n per 8-lane group = 32B sector
    float* base = zhat + (size_t)b * (C_ * N_) + n0;
#pragma unroll
    for (int mt = 0; mt < 4; ++mt) {
        int nn = wm * 64 + mt * 16 + g;
#pragma unroll
        for (int nt = 0; nt < 4; ++nt) {
            int col = c0 + wn * 32 + nt * 8 + 2 * tg;
            base[(size_t)col * N_ + nn]           = acc[mt][nt][0];
            base[(size_t)(col + 1) * N_ + nn]     = acc[mt][nt][1];
            base[(size_t)col * N_ + nn + 8]       = acc[mt][nt][2];
            base[(size_t)(col + 1) * N_ + nn + 8] = acc[mt][nt][3];
        }
    }
}

// ---------------------------------------------------------------------------
extern "C" void kernel_launch(void* const* d_in, const int* in_sizes, int n_in,
                              void* d_out, int out_size) {
    const float* z   = (const float*)d_in[0];
    const float* mem = (const float*)d_in[1];
    float* zhat = (float*)d_out;
    float* attn = zhat + (size_t)B_ * C_ * N_;

    cudaFuncSetAttribute(k_gemm1_t, cudaFuncAttributeMaxDynamicSharedMemorySize, SMEM_BYTES);
    cudaFuncSetAttribute(k_gemm2_t, cudaFuncAttributeMaxDynamicSharedMemorySize, SMEM_BYTES);

    k_rnorm_z<<<BN_ / 256, 256>>>(z);
    k_rnorm_m<<<M_, 128>>>(mem);
    k_round_mem<<<(M_ * C_ + 1023) / 1024, 1024>>>(mem);
    k_gemm1_t<<<dim3(M_ / 128, BN_ / 128), 256, SMEM_BYTES>>>(z, attn);
    k_softmax<<<BN_, 128>>>(attn);
    k_gemm2_t<<<dim3(C_ / 128, BN_ / 128), 256, SMEM_BYTES>>>(attn, zhat);
}

// round 5
// speedup vs baseline: 4.3159x; 1.3203x over previous
#include <cuda_runtime.h>
#include <cuda_fp16.h>
#include <math.h>
#include <stdint.h>

#define B_  16
#define C_  768
#define N_  4096
#define BN_ 65536
#define M_  1024

#define KC      64                  // K halves per pipeline chunk (4 x k16 mma)
#define STR     72                  // padded smem row stride in halves
#define STAGES  3
#define STAGE_BYTES (128 * STR * 2)            // 18432 B per operand per stage
#define DYN_SMEM (STAGES * 2 * STAGE_BYTES)    // 110592 B

// scratch (allocation-free __device__ globals)
__device__ __half g_zh[(size_t)BN_ * C_];     // half(z * rz), K-major [bn][c]
__device__ __half g_memh[M_ * C_];            // half(mem * rm)        [m][c]
__device__ __half g_memTh[C_ * M_];           // half(mem) transposed  [c][m]
__device__ __half g_attnh[(size_t)BN_ * M_];  // half(attn)            [bn][m]
__device__ float  g_rm[M_];

// ---------------------------------------------------------------- helpers ---
__device__ __forceinline__ uint32_t smem_u32(const void* p) {
    uint32_t a;
    asm("{ .reg .u64 t; cvta.to.shared.u64 t, %1; cvt.u32.u64 %0, t; }"
        : "=r"(a) : "l"(p));
    return a;
}
__device__ __forceinline__ void cp16(uint32_t dst, const void* src) {
    asm volatile("cp.async.cg.shared.global [%0], [%1], 16;" :: "r"(dst), "l"(src));
}
__device__ __forceinline__ void cp_commit() {
    asm volatile("cp.async.commit_group;\n" ::: "memory");
}
template <int W>
__device__ __forceinline__ void cp_wait() {
    asm volatile("cp.async.wait_group %0;\n" :: "n"(W) : "memory");
}
__device__ __forceinline__ void mma16(float* d, const uint32_t* a, const uint32_t* b) {
    asm volatile(
        "mma.sync.aligned.m16n8k16.row.col.f32.f16.f16.f32 "
        "{%0,%1,%2,%3}, {%4,%5,%6,%7}, {%8,%9}, {%0,%1,%2,%3};\n"
        : "+f"(d[0]), "+f"(d[1]), "+f"(d[2]), "+f"(d[3])
        : "r"(a[0]), "r"(a[1]), "r"(a[2]), "r"(a[3]), "r"(b[0]), "r"(b[1]));
}

// stage loader: 128 rows x KC halves each for A and B, 16B per cp.async
__device__ __forceinline__ void load_tile(uint32_t dstA, uint32_t dstB,
                                          const __half* srcA, const __half* srcB,
                                          int tid, int ldA, int ldB) {
#pragma unroll
    for (int q = 0; q < 4; ++q) {
        int e = q * 256 + tid;
        int r = e >> 3, kq = e & 7;
        cp16(dstA + r * (STR * 2) + kq * 16, srcA + (size_t)r * ldA + kq * 8);
    }
#pragma unroll
    for (int q = 0; q < 4; ++q) {
        int e = q * 256 + tid;
        int r = e >> 3, kq = e & 7;
        cp16(dstB + r * (STR * 2) + kq * 16, srcB + (size_t)r * ldB + kq * 8);
    }
}

// ------------------------------------------------------------- GEMM core ----
// D[128 x 128] = A[128 x K] * B[128 x K]^T, fp16 inputs, fp32 accumulators.
// 8 warps as 2x4; warp tile 64x32; 3-stage cp.async pipeline, wait_group 1.
// acc layout: acc[mt][nt][q] per warp; fragment rows = wm*64+mt*16+g (+8),
// cols = wn*32+nt*8+2*tg (+1).
__device__ __forceinline__ void gemm_main(char* sm_, int T_,
                                          const __half* Asrc, const __half* Bsrc,
                                          int ldA, int ldB, int tid,
                                          int wm, int wn, int g, int tg,
                                          float acc[4][4][4]) {
#pragma unroll
    for (int i = 0; i < 4; ++i)
#pragma unroll
        for (int j = 0; j < 4; ++j)
#pragma unroll
            for (int q = 0; q < 4; ++q) acc[i][j][q] = 0.f;

    uint32_t Asm = smem_u32(sm_);
    uint32_t Bsm = Asm + STAGES * STAGE_BYTES;

    load_tile(Asm, Bsm, Asrc, Bsrc, tid, ldA, ldB);
    cp_commit();
    load_tile(Asm + STAGE_BYTES, Bsm + STAGE_BYTES, Asrc + KC, Bsrc + KC,
              tid, ldA, ldB);
    cp_commit();

    for (int it = 0; it < T_; ++it) {
        cp_wait<1>();
        __syncthreads();
        if (it + 2 < T_) {
            int s = (it + 2) % STAGES;
            load_tile(Asm + s * STAGE_BYTES, Bsm + s * STAGE_BYTES,
                      Asrc + (size_t)(it + 2) * KC, Bsrc + (size_t)(it + 2) * KC,
                      tid, ldA, ldB);
        }
        cp_commit();
        const __half* A = (const __half*)(sm_ + (it % STAGES) * STAGE_BYTES);
        const __half* Bq = (const __half*)(sm_ + STAGES * STAGE_BYTES +
                                           (it % STAGES) * STAGE_BYTES);
#pragma unroll
        for (int kk = 0; kk < KC; kk += 16) {
            uint32_t af[4][4], bf[4][2];
#pragma unroll
            for (int mt = 0; mt < 4; ++mt) {
                int r = wm * 64 + mt * 16 + g;
                af[mt][0] = *(const uint32_t*)(A + r * STR + kk + 2 * tg);
                af[mt][1] = *(const uint32_t*)(A + (r + 8) * STR + kk + 2 * tg);
                af[mt][2] = *(const uint32_t*)(A + r * STR + kk + 8 + 2 * tg);
                af[mt][3] = *(const uint32_t*)(A + (r + 8) * STR + kk + 8 + 2 * tg);
            }
#pragma unroll
            for (int nt = 0; nt < 4; ++nt) {
                int nn = wn * 32 + nt * 8 + g;
                bf[nt][0] = *(const uint32_t*)(Bq + nn * STR + kk + 2 * tg);
                bf[nt][1] = *(const uint32_t*)(Bq + nn * STR + kk + 8 + 2 * tg);
            }
#pragma unroll
            for (int mt = 0; mt < 4; ++mt)
#pragma unroll
                for (int nt = 0; nt < 4; ++nt) mma16(acc[mt][nt], af[mt], bf[nt]);
        }
        __syncthreads();
    }
}

// ---------------------------------------------------------------- prep ------
__global__ void k_rnorm_m(const float* __restrict__ mem) {
    int m = blockIdx.x;
    const float* p = mem + m * C_;
    float acc = 0.f;
    for (int c = threadIdx.x; c < C_; c += 128) {
        float v = p[c];
        acc = fmaf(v, v, acc);
    }
#pragma unroll
    for (int o = 16; o; o >>= 1) acc += __shfl_xor_sync(0xffffffffu, acc, o);
    __shared__ float s[4];
    if ((threadIdx.x & 31) == 0) s[threadIdx.x >> 5] = acc;
    __syncthreads();
    if (threadIdx.x == 0)
        g_rm[m] = 1.0f / fmaxf(sqrtf(s[0] + s[1] + s[2] + s[3]), 1e-12f);
}

// memh = half(mem*rm) [m][c];  memTh = half(mem) transposed [c][m]
__global__ void k_prep(const float* __restrict__ mem) {
    __shared__ float t[32][33];
    int c0 = blockIdx.x << 5, m0 = blockIdx.y << 5;
    int tx = threadIdx.x, ty = threadIdx.y;
    float v = mem[(size_t)(m0 + ty) * C_ + c0 + tx];
    g_memh[(size_t)(m0 + ty) * C_ + c0 + tx] = __float2half_rn(v * g_rm[m0 + ty]);
    t[ty][tx] = v;
    __syncthreads();
    g_memTh[(size_t)(c0 + ty) * M_ + m0 + tx] = __float2half_rn(t[tx][ty]);
}

// zh[bn][c] = half(z[b,c,n] * rz[bn])  — fused transpose + L2 norm
__global__ void __launch_bounds__(256) k_zt_h(const float* __restrict__ z) {
    extern __shared__ float tile[];   // [768][33]
    __shared__ float part[8][32];
    __shared__ float rzv[32];
    int blk = blockIdx.x;
    int b = blk >> 7;
    int n0 = (blk & 127) << 5;
    const float* zb = z + (size_t)b * (C_ * N_) + n0;
    int tid = threadIdx.x;
    for (int e = tid; e < C_ * 32; e += 256) {
        int c = e >> 5, nl = e & 31;
        tile[c * 33 + nl] = zb[(size_t)c * N_ + nl];
    }
    __syncthreads();
    {
        int col = tid & 31, j = tid >> 5;
        float acc = 0.f;
        for (int c = j; c < C_; c += 8) {
            float v = tile[c * 33 + col];
            acc = fmaf(v, v, acc);
        }
        part[j][col] = acc;
    }
    __syncthreads();
    if (tid < 32) {
        float s = 0.f;
#pragma unroll
        for (int j = 0; j < 8; ++j) s += part[j][tid];
        rzv[tid] = 1.0f / fmaxf(sqrtf(s), 1e-12f);
    }
    __syncthreads();
    __half* out = g_zh + (size_t)(b * N_ + n0) * C_;
    for (int e = tid; e < C_ * 32; e += 256) {
        int nl = e / C_;
        int c = e - nl * C_;
        out[(size_t)nl * C_ + c] = __float2half_rn(tile[c * 33 + nl] * rzv[nl]);
    }
}

// ---------------------------------------------------------------- GEMM1 -----
// scores[row][m] = sum_c zh[row][c] * memh[m][c]
__global__ void __launch_bounds__(256) k_gemm1_h(float* __restrict__ scores) {
    extern __shared__ __align__(128) char sm_[];
    const int tid = threadIdx.x, lane = tid & 31, warp = tid >> 5;
    const int g = lane >> 2, tg = lane & 3;
    const int wm = warp >> 2, wn = warp & 3;
    const int m0 = blockIdx.x * 128;
    const int row0 = blockIdx.y * 128;

    float acc[4][4][4];
    gemm_main(sm_, C_ / KC, g_zh + (size_t)row0 * C_, g_memh + (size_t)m0 * C_,
              C_, C_, tid, wm, wn, g, tg, acc);

#pragma unroll
    for (int mt = 0; mt < 4; ++mt) {
        int r = row0 + wm * 64 + mt * 16 + g;
#pragma unroll
        for (int nt = 0; nt < 4; ++nt) {
            int col = m0 + wn * 32 + nt * 8 + 2 * tg;
            float2 o;
            o.x = acc[mt][nt][0];
            o.y = acc[mt][nt][1];
            *(float2*)(scores + (size_t)r * M_ + col) = o;
            o.x = acc[mt][nt][2];
            o.y = acc[mt][nt][3];
            *(float2*)(scores + (size_t)(r + 8) * M_ + col) = o;
        }
    }
}

// ---------------------------------------------------------------- GEMM2 -----
// zhat[b,c,n] = sum_m attnh[row][m] * memTh[c][m]
__global__ void __launch_bounds__(256) k_gemm2_h(float* __restrict__ zhat) {
    extern __shared__ __align__(128) char sm_[];
    const int tid = threadIdx.x, lane = tid & 31, warp = tid >> 5;
    const int g = lane >> 2, tg = lane & 3;
    const int wm = warp >> 2, wn = warp & 3;
    const int c0 = blockIdx.x * 128;
    const int row0 = blockIdx.y * 128;

    float acc[4][4][4];
    gemm_main(sm_, M_ / KC, g_attnh + (size_t)row0 * M_, g_memTh + (size_t)c0 * M_,
              M_, M_, tid, wm, wn, g, tg, acc);

    const int b = row0 >> 12;
    const int n0 = row0 & (N_ - 1);
    float* base = zhat + (size_t)b * (C_ * N_) + n0;
#pragma unroll
    for (int mt = 0; mt < 4; ++mt) {
        int nn = wm * 64 + mt * 16 + g;
#pragma unroll
        for (int nt = 0; nt < 4; ++nt) {
            int col = c0 + wn * 32 + nt * 8 + 2 * tg;
            base[(size_t)col * N_ + nn]           = acc[mt][nt][0];
            base[(size_t)(col + 1) * N_ + nn]     = acc[mt][nt][1];
            base[(size_t)col * N_ + nn + 8]       = acc[mt][nt][2];
            base[(size_t)(col + 1) * N_ + nn + 8] = acc[mt][nt][3];
        }
    }
}

// ---------------------------------------------------------------- softmax ---
// float attn (exact output to d_out) + half copy for GEMM2
__global__ void k_softmax(float* __restrict__ attn) {
    const size_t row = blockIdx.x;
    float* p = attn + row * M_;
    const int t = threadIdx.x;
    float v[8];
    *(float4*)(v)     = *(const float4*)(p + t * 8);
    *(float4*)(v + 4) = *(const float4*)(p + t * 8 + 4);
    float mx = v[0];
#pragma unroll
    for (int i = 1; i < 8; ++i) mx = fmaxf(mx, v[i]);
#pragma unroll
    for (int o = 16; o; o >>= 1) mx = fmaxf(mx, __shfl_xor_sync(0xffffffffu, mx, o));
    __shared__ float red[4];
    if ((t & 31) == 0) red[t >> 5] = mx;
    __syncthreads();
    mx = fmaxf(fmaxf(red[0], red[1]), fmaxf(red[2], red[3]));
    __syncthreads();
    float sum = 0.f;
#pragma unroll
    for (int i = 0; i < 8; ++i) {
        v[i] = expf(v[i] - mx);
        sum += v[i];
    }
#pragma unroll
    for (int o = 16; o; o >>= 1) sum += __shfl_xor_sync(0xffffffffu, sum, o);
    if ((t & 31) == 0) red[t >> 5] = sum;
    __syncthreads();
    sum = red[0] + red[1] + red[2] + red[3];
    float r = 1.0f / sum;
#pragma unroll
    for (int i = 0; i < 8; ++i) v[i] *= r;
    *(float4*)(p + t * 8)     = *(const float4*)(v);
    *(float4*)(p + t * 8 + 4) = *(const float4*)(v + 4);
    __half2 h0 = __floats2half2_rn(v[0], v[1]);
    __half2 h1 = __floats2half2_rn(v[2], v[3]);
    __half2 h2 = __floats2half2_rn(v[4], v[5]);
    __half2 h3 = __floats2half2_rn(v[6], v[7]);
    uint4 u;
    u.x = *(uint32_t*)&h0;
    u.y = *(uint32_t*)&h1;
    u.z = *(uint32_t*)&h2;
    u.w = *(uint32_t*)&h3;
    *(uint4*)(g_attnh + row * M_ + t * 8) = u;
}

// ---------------------------------------------------------------------------
extern "C" void kernel_launch(void* const* d_in, const int* in_sizes, int n_in,
                              void* d_out, int out_size) {
    const float* z   = (const float*)d_in[0];
    const float* mem = (const float*)d_in[1];
    float* zhat = (float*)d_out;
    float* attn = zhat + (size_t)B_ * C_ * N_;

    cudaFuncSetAttribute(k_zt_h, cudaFuncAttributeMaxDynamicSharedMemorySize, C_ * 33 * 4);
    cudaFuncSetAttribute(k_gemm1_h, cudaFuncAttributeMaxDynamicSharedMemorySize, DYN_SMEM);
    cudaFuncSetAttribute(k_gemm2_h, cudaFuncAttributeMaxDynamicSharedMemorySize, DYN_SMEM);

    k_rnorm_m<<<M_, 128>>>(mem);
    k_prep<<<dim3(C_ / 32, M_ / 32), dim3(32, 32)>>>(mem);
    k_zt_h<<<BN_ / 32, 256, C_ * 33 * 4>>>(z);
    k_gemm1_h<<<dim3(M_ / 128, BN_ / 128), 256, DYN_SMEM>>>(attn);
    k_softmax<<<BN_, 128>>>(attn);
    k_gemm2_h<<<dim3(C_ / 128, BN_ / 128), 256, DYN_SMEM>>>(zhat);
}

// round 6
// speedup vs baseline: 5.2533x; 1.2172x over previous
#include <cuda_runtime.h>
#include <cuda_fp16.h>
#include <math.h>
#include <stdint.h>

#define B_  16
#define C_  768
#define N_  4096
#define BN_ 65536
#define M_  1024

#define KC      64                   // K halves per pipeline chunk (4 x k16 mma)
#define STAGES  3
#define STAGE_BYTES (128 * 128)      // 128 rows x 64 halves, swizzled, no pad
#define DYN_SMEM (STAGES * 2 * STAGE_BYTES)   // 98304 B -> 2 CTAs/SM

// scratch (allocation-free __device__ globals)
__device__ __half g_zh[(size_t)BN_ * C_];     // half(z * rz), K-major [bn][c]
__device__ __half g_memh[M_ * C_];            // half(mem * rm)        [m][c]
__device__ __half g_memTh[C_ * M_];           // half(mem) transposed  [c][m]
__device__ __half g_attnh[(size_t)BN_ * M_];  // half(attn)            [bn][m]
__device__ float  g_rm[M_];

// ---------------------------------------------------------------- helpers ---
__device__ __forceinline__ uint32_t smem_u32(const void* p) {
    uint32_t a;
    asm("{ .reg .u64 t; cvta.to.shared.u64 t, %1; cvt.u32.u64 %0, t; }"
        : "=r"(a) : "l"(p));
    return a;
}
__device__ __forceinline__ void cp16(uint32_t dst, const void* src) {
    asm volatile("cp.async.cg.shared.global [%0], [%1], 16;" :: "r"(dst), "l"(src));
}
__device__ __forceinline__ void cp_commit() {
    asm volatile("cp.async.commit_group;\n" ::: "memory");
}
template <int W>
__device__ __forceinline__ void cp_wait() {
    asm volatile("cp.async.wait_group %0;\n" :: "n"(W) : "memory");
}
__device__ __forceinline__ void mma16(float* d, const uint32_t* a, const uint32_t* b) {
    asm volatile(
        "mma.sync.aligned.m16n8k16.row.col.f32.f16.f16.f32 "
        "{%0,%1,%2,%3}, {%4,%5,%6,%7}, {%8,%9}, {%0,%1,%2,%3};\n"
        : "+f"(d[0]), "+f"(d[1]), "+f"(d[2]), "+f"(d[3])
        : "r"(a[0]), "r"(a[1]), "r"(a[2]), "r"(a[3]), "r"(b[0]), "r"(b[1]));
}
__device__ __forceinline__ void ldm_x4(uint32_t* r, uint32_t addr) {
    asm volatile("ldmatrix.sync.aligned.m8n8.x4.shared.b16 {%0,%1,%2,%3}, [%4];"
                 : "=r"(r[0]), "=r"(r[1]), "=r"(r[2]), "=r"(r[3]) : "r"(addr));
}

// swizzled physical byte offset: row r (stride 128B), 16B chunk c -> c ^ (r&7)
__device__ __forceinline__ uint32_t swz(int r, int c) {
    return (uint32_t)(r * 128) + (uint32_t)((c ^ (r & 7)) << 4);
}

// stage loader: 128 rows x KC halves each for A and B, 16B per cp.async
__device__ __forceinline__ void load_tile(uint32_t dstA, uint32_t dstB,
                                          const __half* srcA, const __half* srcB,
                                          int tid, int ldA, int ldB) {
#pragma unroll
    for (int q = 0; q < 4; ++q) {
        int e = q * 256 + tid;
        int r = e >> 3, kq = e & 7;
        cp16(dstA + swz(r, kq), srcA + (size_t)r * ldA + kq * 8);
    }
#pragma unroll
    for (int q = 0; q < 4; ++q) {
        int e = q * 256 + tid;
        int r = e >> 3, kq = e & 7;
        cp16(dstB + swz(r, kq), srcB + (size_t)r * ldB + kq * 8);
    }
}

// ------------------------------------------------------------- GEMM core ----
// D[128 x 128] = A[128 x K] * B[128 x K]^T, fp16 in, fp32 acc.
// 8 warps as 2x4; warp tile 64x32; 3-stage cp.async pipeline; ldmatrix frags.
__device__ __forceinline__ void gemm_main(char* sm_, int T_,
                                          const __half* Asrc, const __half* Bsrc,
                                          int ldA, int ldB, int tid,
                                          int wm, int wn, int lane,
                                          float acc[4][4][4]) {
#pragma unroll
    for (int i = 0; i < 4; ++i)
#pragma unroll
        for (int j = 0; j < 4; ++j)
#pragma unroll
            for (int q = 0; q < 4; ++q) acc[i][j][q] = 0.f;

    uint32_t Asm = smem_u32(sm_);
    uint32_t Bsm = Asm + STAGES * STAGE_BYTES;

    const int l7 = lane & 7, lg = lane >> 3;          // lg: 0..3
    // ldmatrix per-lane rows (see fragment mapping comments below)
    int rowA[4], rowB[2];
#pragma unroll
    for (int mt = 0; mt < 4; ++mt) rowA[mt] = wm * 64 + mt * 16 + (lg & 1) * 8 + l7;
#pragma unroll
    for (int p = 0; p < 2; ++p)    rowB[p] = wn * 32 + p * 16 + (lg >> 1) * 8 + l7;
    const int cA = lg >> 1;                            // A chunk offset for this lane
    const int cB = lg & 1;                             // B chunk offset

    load_tile(Asm, Bsm, Asrc, Bsrc, tid, ldA, ldB);
    cp_commit();
    load_tile(Asm + STAGE_BYTES, Bsm + STAGE_BYTES, Asrc + KC, Bsrc + KC,
              tid, ldA, ldB);
    cp_commit();

    for (int it = 0; it < T_; ++it) {
        cp_wait<1>();
        __syncthreads();
        if (it + 2 < T_) {
            int s = (it + 2) % STAGES;
            load_tile(Asm + s * STAGE_BYTES, Bsm + s * STAGE_BYTES,
                      Asrc + (size_t)(it + 2) * KC, Bsrc + (size_t)(it + 2) * KC,
                      tid, ldA, ldB);
        }
        cp_commit();
        uint32_t Ab = Asm + (it % STAGES) * STAGE_BYTES;
        uint32_t Bb = Bsm + (it % STAGES) * STAGE_BYTES;
#pragma unroll
        for (int kk = 0; kk < KC; kk += 16) {
            const int ck = kk >> 3;
            uint32_t af[4][4], bf[4][2];
            // A x4: matrices = (rows m..m+7,k) (m+8..m+15,k) (m..m+7,k+8) (m+8..,k+8)
#pragma unroll
            for (int mt = 0; mt < 4; ++mt)
                ldm_x4(af[mt], Ab + swz(rowA[mt], ck + cA));
            // B x4 per nt-pair: regs -> bf[2p][0], bf[2p][1], bf[2p+1][0], bf[2p+1][1]
#pragma unroll
            for (int p = 0; p < 2; ++p) {
                uint32_t t[4];
                ldm_x4(t, Bb + swz(rowB[p], ck + cB));
                bf[2 * p][0] = t[0];
                bf[2 * p][1] = t[1];
                bf[2 * p + 1][0] = t[2];
                bf[2 * p + 1][1] = t[3];
            }
#pragma unroll
            for (int mt = 0; mt < 4; ++mt)
#pragma unroll
                for (int nt = 0; nt < 4; ++nt) mma16(acc[mt][nt], af[mt], bf[nt]);
        }
        __syncthreads();
    }
}

// ---------------------------------------------------------------- prep ------
__global__ void k_rnorm_m(const float* __restrict__ mem) {
    int m = blockIdx.x;
    const float* p = mem + m * C_;
    float acc = 0.f;
    for (int c = threadIdx.x; c < C_; c += 128) {
        float v = p[c];
        acc = fmaf(v, v, acc);
    }
#pragma unroll
    for (int o = 16; o; o >>= 1) acc += __shfl_xor_sync(0xffffffffu, acc, o);
    __shared__ float s[4];
    if ((threadIdx.x & 31) == 0) s[threadIdx.x >> 5] = acc;
    __syncthreads();
    if (threadIdx.x == 0)
        g_rm[m] = 1.0f / fmaxf(sqrtf(s[0] + s[1] + s[2] + s[3]), 1e-12f);
}

// memh = half(mem*rm) [m][c];  memTh = half(mem) transposed [c][m]
__global__ void k_prep(const float* __restrict__ mem) {
    __shared__ float t[32][33];
    int c0 = blockIdx.x << 5, m0 = blockIdx.y << 5;
    int tx = threadIdx.x, ty = threadIdx.y;
    float v = mem[(size_t)(m0 + ty) * C_ + c0 + tx];
    g_memh[(size_t)(m0 + ty) * C_ + c0 + tx] = __float2half_rn(v * g_rm[m0 + ty]);
    t[ty][tx] = v;
    __syncthreads();
    g_memTh[(size_t)(c0 + ty) * M_ + m0 + tx] = __float2half_rn(t[tx][ty]);
}

// zh[bn][c] = half(z[b,c,n] * rz[bn])  — fused transpose + L2 norm
__global__ void __launch_bounds__(256) k_zt_h(const float* __restrict__ z) {
    extern __shared__ float tile[];   // [768][33]
    __shared__ float part[8][32];
    __shared__ float rzv[32];
    int blk = blockIdx.x;
    int b = blk >> 7;
    int n0 = (blk & 127) << 5;
    const float* zb = z + (size_t)b * (C_ * N_) + n0;
    int tid = threadIdx.x;
    for (int e = tid; e < C_ * 32; e += 256) {
        int c = e >> 5, nl = e & 31;
        tile[c * 33 + nl] = zb[(size_t)c * N_ + nl];
    }
    __syncthreads();
    {
        int col = tid & 31, j = tid >> 5;
        float acc = 0.f;
        for (int c = j; c < C_; c += 8) {
            float v = tile[c * 33 + col];
            acc = fmaf(v, v, acc);
        }
        part[j][col] = acc;
    }
    __syncthreads();
    if (tid < 32) {
        float s = 0.f;
#pragma unroll
        for (int j = 0; j < 8; ++j) s += part[j][tid];
        rzv[tid] = 1.0f / fmaxf(sqrtf(s), 1e-12f);
    }
    __syncthreads();
    __half* out = g_zh + (size_t)(b * N_ + n0) * C_;
    for (int e = tid; e < C_ * 32; e += 256) {
        int nl = e / C_;
        int c = e - nl * C_;
        out[(size_t)nl * C_ + c] = __float2half_rn(tile[c * 33 + nl] * rzv[nl]);
    }
}

// ---------------------------------------------------------------- GEMM1 -----
// scores[row][m] = sum_c zh[row][c] * memh[m][c]
__global__ void __launch_bounds__(256, 2) k_gemm1_h(float* __restrict__ scores) {
    extern __shared__ __align__(128) char sm_[];
    const int tid = threadIdx.x, lane = tid & 31, warp = tid >> 5;
    const int g = lane >> 2, tg = lane & 3;
    const int wm = warp >> 2, wn = warp & 3;
    const int m0 = blockIdx.x * 128;
    const int row0 = blockIdx.y * 128;

    float acc[4][4][4];
    gemm_main(sm_, C_ / KC, g_zh + (size_t)row0 * C_, g_memh + (size_t)m0 * C_,
              C_, C_, tid, wm, wn, lane, acc);

#pragma unroll
    for (int mt = 0; mt < 4; ++mt) {
        int r = row0 + wm * 64 + mt * 16 + g;
#pragma unroll
        for (int nt = 0; nt < 4; ++nt) {
            int col = m0 + wn * 32 + nt * 8 + 2 * tg;
            float2 o;
            o.x = acc[mt][nt][0];
            o.y = acc[mt][nt][1];
            *(float2*)(scores + (size_t)r * M_ + col) = o;
            o.x = acc[mt][nt][2];
            o.y = acc[mt][nt][3];
            *(float2*)(scores + (size_t)(r + 8) * M_ + col) = o;
        }
    }
}

// ---------------------------------------------------------------- GEMM2 -----
// zhat[b,c,n] = sum_m attnh[row][m] * memTh[c][m]
__global__ void __launch_bounds__(256, 2) k_gemm2_h(float* __restrict__ zhat) {
    extern __shared__ __align__(128) char sm_[];
    const int tid = threadIdx.x, lane = tid & 31, warp = tid >> 5;
    const int g = lane >> 2, tg = lane & 3;
    const int wm = warp >> 2, wn = warp & 3;
    const int c0 = blockIdx.x * 128;
    const int row0 = blockIdx.y * 128;

    float acc[4][4][4];
    gemm_main(sm_, M_ / KC, g_attnh + (size_t)row0 * M_, g_memTh + (size_t)c0 * M_,
              M_, M_, tid, wm, wn, lane, acc);

    const int b = row0 >> 12;
    const int n0 = row0 & (N_ - 1);
    float* base = zhat + (size_t)b * (C_ * N_) + n0;
#pragma unroll
    for (int mt = 0; mt < 4; ++mt) {
        int nn = wm * 64 + mt * 16 + g;
#pragma unroll
        for (int nt = 0; nt < 4; ++nt) {
            int col = c0 + wn * 32 + nt * 8 + 2 * tg;
            base[(size_t)col * N_ + nn]           = acc[mt][nt][0];
            base[(size_t)(col + 1) * N_ + nn]     = acc[mt][nt][1];
            base[(size_t)col * N_ + nn + 8]       = acc[mt][nt][2];
            base[(size_t)(col + 1) * N_ + nn + 8] = acc[mt][nt][3];
        }
    }
}

// ---------------------------------------------------------------- softmax ---
// float attn (exact output to d_out) + half copy for GEMM2
__global__ void k_softmax(float* __restrict__ attn) {
    const size_t row = blockIdx.x;
    float* p = attn + row * M_;
    const int t = threadIdx.x;
    float v[8];
    *(float4*)(v)     = *(const float4*)(p + t * 8);
    *(float4*)(v + 4) = *(const float4*)(p + t * 8 + 4);
    float mx = v[0];
#pragma unroll
    for (int i = 1; i < 8; ++i) mx = fmaxf(mx, v[i]);
#pragma unroll
    for (int o = 16; o; o >>= 1) mx = fmaxf(mx, __shfl_xor_sync(0xffffffffu, mx, o));
    __shared__ float red[4];
    if ((t & 31) == 0) red[t >> 5] = mx;
    __syncthreads();
    mx = fmaxf(fmaxf(red[0], red[1]), fmaxf(red[2], red[3]));
    __syncthreads();
    float sum = 0.f;
#pragma unroll
    for (int i = 0; i < 8; ++i) {
        v[i] = expf(v[i] - mx);
        sum += v[i];
    }
#pragma unroll
    for (int o = 16; o; o >>= 1) sum += __shfl_xor_sync(0xffffffffu, sum, o);
    if ((t & 31) == 0) red[t >> 5] = sum;
    __syncthreads();
    sum = red[0] + red[1] + red[2] + red[3];
    float r = 1.0f / sum;
#pragma unroll
    for (int i = 0; i < 8; ++i) v[i] *= r;
    *(float4*)(p + t * 8)     = *(const float4*)(v);
    *(float4*)(p + t * 8 + 4) = *(const float4*)(v + 4);
    __half2 h0 = __floats2half2_rn(v[0], v[1]);
    __half2 h1 = __floats2half2_rn(v[2], v[3]);
    __half2 h2 = __floats2half2_rn(v[4], v[5]);
    __half2 h3 = __floats2half2_rn(v[6], v[7]);
    uint4 u;
    u.x = *(uint32_t*)&h0;
    u.y = *(uint32_t*)&h1;
    u.z = *(uint32_t*)&h2;
    u.w = *(uint32_t*)&h3;
    *(uint4*)(g_attnh + row * M_ + t * 8) = u;
}

// ---------------------------------------------------------------------------
extern "C" void kernel_launch(void* const* d_in, const int* in_sizes, int n_in,
                              void* d_out, int out_size) {
    const float* z   = (const float*)d_in[0];
    const float* mem = (const float*)d_in[1];
    float* zhat = (float*)d_out;
    float* attn = zhat + (size_t)B_ * C_ * N_;

    cudaFuncSetAttribute(k_zt_h, cudaFuncAttributeMaxDynamicSharedMemorySize, C_ * 33 * 4);
    cudaFuncSetAttribute(k_gemm1_h, cudaFuncAttributeMaxDynamicSharedMemorySize, DYN_SMEM);
    cudaFuncSetAttribute(k_gemm2_h, cudaFuncAttributeMaxDynamicSharedMemorySize, DYN_SMEM);

    k_rnorm_m<<<M_, 128>>>(mem);
    k_prep<<<dim3(C_ / 32, M_ / 32), dim3(32, 32)>>>(mem);
    k_zt_h<<<BN_ / 32, 256, C_ * 33 * 4>>>(z);
    k_gemm1_h<<<dim3(M_ / 128, BN_ / 128), 256, DYN_SMEM>>>(attn);
    k_softmax<<<BN_, 128>>>(attn);
    k_gemm2_h<<<dim3(C_ / 128, BN_ / 128), 256, DYN_SMEM>>>(zhat);
}